// round 8
// baseline (speedup 1.0000x reference)
#include <cuda_runtime.h>

// ---------------- problem constants ----------------
#define BB   32      // batch
#define SS   256     // seq len
#define II   128     // input dim
#define HH   512     // hidden
#define CC   64      // out channels
#define DD   17      // buffer depth (MAX_DELAY+1)
#define TENC 256
#define TDEC 64

// ---------------- kernel config ----------------
#define NBLK 128     // blocks (<=148 SMs -> all resident, barrier-safe)
#define NTHR 256     // threads per block
#define NC   4       // hidden columns per block (NBLK*NC == HH)
#define IROW 644     // padded input row stride (floats) -> conflict-free
#define WSI  648     // padded W_in column stride
#define WSH  520     // padded 512-row weight column stride

struct Smem {
    // float4-accessed arrays first (16B-aligned offsets)
    float inp[BB * IROW];          // staged activations (32 x up-to-640)
    float w_in [NC * WSI];         // W_in[:, jb..jb+3] transposed (col-major)
    float w_ps [NC * WSH];
    float w_tu [NC * WSH];
    float w_me [NC * WSH];
    float w_ot [HH];               // W_out[:, blk] (blocks 0..63 only)
    // scalar-accessed
    float buf[BB * NC * DD];       // circular delay buffer, stride 17 (odd -> conflict-free)
    float h1s[BB * NC];
    float hs [BB * NC];
    float psA[NTHR];
    float psB[NTHR];
    float psO[64];
    float sb_in[NC], sb_ps[NC], sb_tu[NC], sb_me[NC];
    float sb_ot;
    int   len[BB];
};

__device__ float g_h0[BB * HH];
__device__ float g_h1[BB * HH];
__device__ float g_hx[BB * HH];
__device__ unsigned g_arr;
__device__ unsigned g_gen;

// sense-reversing grid barrier (all NBLK blocks resident by construction)
__device__ __forceinline__ void grid_sync() {
    __syncthreads();
    if (threadIdx.x == 0) {
        volatile unsigned* vg = &g_gen;
        unsigned gen = *vg;
        __threadfence();                       // release my block's stores (cumulative)
        if (atomicAdd(&g_arr, 1u) == NBLK - 1u) {
            g_arr = 0u;
            __threadfence();
            atomicAdd(&g_gen, 1u);
        } else {
            while (*vg == gen) { }
            __threadfence();                   // acquire
        }
    }
    __syncthreads();
}

// one recurrence step (encode: DEC=false uses x_t + mask; decode: DEC=true, emits out)
template<bool DEC>
__device__ __forceinline__ void rnn_step(
    Smem* s, const float* __restrict__ x, float* __restrict__ out,
    int g, int t, int jb, int blk, int tid, int c, int b, int half)
{
    // ================= phase 1: h1 = [h0, x_t] @ W_in + b_in =================
    for (int i = tid; i < BB * (HH / 4); i += NTHR) {
        int rb = i >> 7, k4 = i & 127;
        float4 v = __ldcg(reinterpret_cast<const float4*>(g_h0 + rb * HH + (k4 << 2)));
        *reinterpret_cast<float4*>(s->inp + rb * IROW + (k4 << 2)) = v;
    }
    if (!DEC) {
        for (int i = tid; i < BB * (II / 4); i += NTHR) {
            int rb = i >> 5, k4 = i & 31;
            float4 v = *reinterpret_cast<const float4*>(
                x + (size_t)rb * (SS * II) + (size_t)t * II + (k4 << 2));
            *reinterpret_cast<float4*>(s->inp + rb * IROW + HH + (k4 << 2)) = v;
        }
    }
    __syncthreads();
    {
        const int K2 = (DEC ? HH : (HH + II)) >> 1;
        const float4* wp = reinterpret_cast<const float4*>(s->w_in + c * WSI + half * K2);
        const float4* ip = reinterpret_cast<const float4*>(s->inp + b * IROW + half * K2);
        float a0 = 0.f, a1 = 0.f, a2 = 0.f, a3 = 0.f;
        if (DEC && blk < CC) {
            // fold out = h0 @ W_out into the same k-loop (block-uniform branch)
            const float4* op = reinterpret_cast<const float4*>(s->w_ot + half * K2);
            float o0 = 0.f, o1 = 0.f, o2 = 0.f, o3 = 0.f;
            #pragma unroll 8
            for (int i = 0; i < K2 / 4; ++i) {
                float4 w = wp[i], v = ip[i], wo = op[i];
                a0 = fmaf(w.x, v.x, a0);  a1 = fmaf(w.y, v.y, a1);
                a2 = fmaf(w.z, v.z, a2);  a3 = fmaf(w.w, v.w, a3);
                o0 = fmaf(wo.x, v.x, o0); o1 = fmaf(wo.y, v.y, o1);
                o2 = fmaf(wo.z, v.z, o2); o3 = fmaf(wo.w, v.w, o3);
            }
            if (c == 0) s->psO[(half << 5) | b] = (o0 + o1) + (o2 + o3);
            s->psA[tid] = (a0 + a1) + (a2 + a3);
        } else {
            #pragma unroll 8
            for (int i = 0; i < K2 / 4; ++i) {
                float4 w = wp[i], v = ip[i];
                a0 = fmaf(w.x, v.x, a0); a1 = fmaf(w.y, v.y, a1);
                a2 = fmaf(w.z, v.z, a2); a3 = fmaf(w.w, v.w, a3);
            }
            s->psA[tid] = (a0 + a1) + (a2 + a3);
        }
    }
    __syncthreads();
    if (tid < 128) {
        float h1 = s->psA[tid] + s->psA[tid + 128] + s->sb_in[c];
        s->h1s[(b << 2) | c] = h1;
        __stcg(&g_h1[b * HH + jb + c], h1);
    }
    if (DEC && blk < CC && tid < BB) {
        float ov = s->psO[tid] + s->psO[tid + 32] + s->sb_ot;
        out[tid * (TDEC * CC) + t * CC + blk] = ov;
    }
    grid_sync();

    // ================= phase 2: p = h1 @ W_pass + b_pass; h = m*p+(1-m)*h1 ===
    for (int i = tid; i < BB * (HH / 4); i += NTHR) {
        int rb = i >> 7, k4 = i & 127;
        float4 v = __ldcg(reinterpret_cast<const float4*>(g_h1 + rb * HH + (k4 << 2)));
        *reinterpret_cast<float4*>(s->inp + rb * IROW + (k4 << 2)) = v;
    }
    __syncthreads();
    {
        const int K2 = HH >> 1;
        const float4* wp = reinterpret_cast<const float4*>(s->w_ps + c * WSH + half * K2);
        const float4* ip = reinterpret_cast<const float4*>(s->inp + b * IROW + half * K2);
        float a0 = 0.f, a1 = 0.f, a2 = 0.f, a3 = 0.f;
        #pragma unroll 8
        for (int i = 0; i < K2 / 4; ++i) {
            float4 w = wp[i], v = ip[i];
            a0 = fmaf(w.x, v.x, a0); a1 = fmaf(w.y, v.y, a1);
            a2 = fmaf(w.z, v.z, a2); a3 = fmaf(w.w, v.w, a3);
        }
        s->psA[tid] = (a0 + a1) + (a2 + a3);
    }
    __syncthreads();
    if (tid < 128) {
        float p = s->psA[tid] + s->psA[tid + 128] + s->sb_ps[c];
        float hv;
        if (DEC) hv = p;
        else     hv = (t < s->len[b]) ? p : s->h1s[(b << 2) | c];  // m in {0,1} -> exact select
        s->hs[(b << 2) | c] = hv;
        __stcg(&g_hx[b * HH + jb + c], hv);
    }
    grid_sync();

    // ============ phase 3: tau/mem gemms + circular buffer update ============
    for (int i = tid; i < BB * (HH / 4); i += NTHR) {
        int rb = i >> 7, k4 = i & 127;
        float4 v = __ldcg(reinterpret_cast<const float4*>(g_hx + rb * HH + (k4 << 2)));
        *reinterpret_cast<float4*>(s->inp + rb * IROW + (k4 << 2)) = v;
    }
    __syncthreads();
    {
        const int K2 = HH >> 1;
        const float4* wt = reinterpret_cast<const float4*>(s->w_tu + c * WSH + half * K2);
        const float4* wm = reinterpret_cast<const float4*>(s->w_me + c * WSH + half * K2);
        const float4* ip = reinterpret_cast<const float4*>(s->inp + b * IROW + half * K2);
        float a0 = 0.f, a1 = 0.f, a2 = 0.f, a3 = 0.f;
        float m0 = 0.f, m1 = 0.f, m2 = 0.f, m3 = 0.f;
        #pragma unroll 4
        for (int i = 0; i < K2 / 4; ++i) {
            float4 v = ip[i];
            float4 w = wt[i];
            a0 = fmaf(w.x, v.x, a0); a1 = fmaf(w.y, v.y, a1);
            a2 = fmaf(w.z, v.z, a2); a3 = fmaf(w.w, v.w, a3);
            float4 u = wm[i];
            m0 = fmaf(u.x, v.x, m0); m1 = fmaf(u.y, v.y, m1);
            m2 = fmaf(u.z, v.z, m2); m3 = fmaf(u.w, v.w, m3);
        }
        s->psA[tid] = (a0 + a1) + (a2 + a3);
        s->psB[tid] = (m0 + m1) + (m2 + m3);
    }
    __syncthreads();
    if (tid < 128) {
        float tl = s->psA[tid] + s->psA[tid + 128] + s->sb_tu[c];
        float ml = s->psB[tid] + s->psB[tid + 128] + s->sb_me[c];
        float tau = 16.f / (1.f + expf(-tl));
        tau = fminf(fmaxf(tau, 1.f), 16.f);
        float mem = 1.f / (1.f + expf(-ml));
        float hv  = s->hs[(b << 2) | c];
        float* bf = s->buf + ((b << 2) | c) * DD;
        // logical k at step g lives at phys (g+k)%17; newbuf[16]=0 -> zero slot g%17,
        // add w_d*h into phys (g+d)%17 for d=1..16, next h0 = phys (g+1)%17
        int s0 = g % DD;
        bf[s0] = 0.f;
        int sl = s0;
        #pragma unroll
        for (int d = 1; d <= 16; ++d) {
            ++sl; if (sl == DD) sl = 0;
            float w = mem / (1.f + fabsf(tau - (float)d));
            bf[sl] = fmaf(w, hv, bf[sl]);
        }
        int s1 = s0 + 1; if (s1 == DD) s1 = 0;
        __stcg(&g_h0[b * HH + jb + c], bf[s1]);
    }
    grid_sync();
}

__global__ void __launch_bounds__(NTHR, 1)
delay_rnn_kernel(const float* __restrict__ x,
                 const int*   __restrict__ lengths,
                 const float* __restrict__ Win,  const float* __restrict__ b_in,
                 const float* __restrict__ Wps,  const float* __restrict__ b_ps,
                 const float* __restrict__ Wtu,  const float* __restrict__ b_tu,
                 const float* __restrict__ Wme,  const float* __restrict__ b_me,
                 const float* __restrict__ Wot,  const float* __restrict__ b_ot,
                 float* __restrict__ out)
{
    extern __shared__ __align__(16) char smem_raw[];
    Smem* s = reinterpret_cast<Smem*>(smem_raw);
    const int tid  = threadIdx.x;
    const int blk  = blockIdx.x;
    const int jb   = blk * NC;
    const int c    = tid & 3;
    const int b    = (tid >> 2) & 31;
    const int half = tid >> 7;

    // -------- one-time setup: weights -> smem (transposed, padded) --------
    for (int i = tid; i < (HH + II) * NC; i += NTHR) {
        int cc = i & 3, k = i >> 2;
        s->w_in[cc * WSI + k] = Win[k * HH + jb + cc];
    }
    for (int i = tid; i < HH * NC; i += NTHR) {
        int cc = i & 3, k = i >> 2;
        s->w_ps[cc * WSH + k] = Wps[k * HH + jb + cc];
        s->w_tu[cc * WSH + k] = Wtu[k * HH + jb + cc];
        s->w_me[cc * WSH + k] = Wme[k * HH + jb + cc];
    }
    if (blk < CC)
        for (int k = tid; k < HH; k += NTHR) s->w_ot[k] = Wot[k * CC + blk];
    if (tid < NC) {
        s->sb_in[tid] = b_in[jb + tid];
        s->sb_ps[tid] = b_ps[jb + tid];
        s->sb_tu[tid] = b_tu[jb + tid];
        s->sb_me[tid] = b_me[jb + tid];
    }
    if (tid == 0) s->sb_ot = (blk < CC) ? b_ot[blk] : 0.f;
    if (tid < BB) s->len[tid] = lengths[tid];
    for (int i = tid; i < BB * NC * DD; i += NTHR) s->buf[i] = 0.f;
    if (tid < 128) __stcg(&g_h0[b * HH + jb + c], 0.f);   // buffer[:,:,0] starts zero
    grid_sync();

    // -------- encode: 256 steps --------
    for (int g = 0; g < TENC; ++g)
        rnn_step<false>(s, x, out, g, g, jb, blk, tid, c, b, half);
    // -------- decode: 64 steps --------
    for (int g = TENC; g < TENC + TDEC; ++g)
        rnn_step<true>(s, x, out, g, g - TENC, jb, blk, tid, c, b, half);
}

extern "C" void kernel_launch(void* const* d_in, const int* in_sizes, int n_in,
                              void* d_out, int out_size) {
    const float* x       = (const float*)d_in[0];
    const int*   lengths = (const int*)d_in[1];
    // locate W_in robustly (out_lengths scalar may or may not occupy index 2)
    int wi = -1;
    for (int i = 2; i < n_in; ++i)
        if (in_sizes[i] == (HH + II) * HH) { wi = i; break; }
    if (wi < 0) wi = 3;
    const float* Win  = (const float*)d_in[wi + 0];
    const float* b_in = (const float*)d_in[wi + 1];
    const float* Wps  = (const float*)d_in[wi + 2];
    const float* b_ps = (const float*)d_in[wi + 3];
    const float* Wtu  = (const float*)d_in[wi + 4];
    const float* b_tu = (const float*)d_in[wi + 5];
    const float* Wme  = (const float*)d_in[wi + 6];
    const float* b_me = (const float*)d_in[wi + 7];
    const float* Wot  = (const float*)d_in[wi + 8];
    const float* b_ot = (const float*)d_in[wi + 9];
    float* out = (float*)d_out;

    size_t smem = sizeof(Smem);
    cudaFuncSetAttribute(delay_rnn_kernel,
                         cudaFuncAttributeMaxDynamicSharedMemorySize, (int)smem);
    delay_rnn_kernel<<<NBLK, NTHR, smem>>>(x, lengths, Win, b_in, Wps, b_ps,
                                           Wtu, b_tu, Wme, b_me, Wot, b_ot, out);
}

// round 9
// speedup vs baseline: 1.0028x; 1.0028x over previous
#include <cuda_runtime.h>

// ---------------- problem constants ----------------
#define BB   32      // batch
#define SS   256     // seq len
#define II   128     // input dim
#define HH   512     // hidden
#define CC   64      // out channels
#define DD   17      // buffer depth (MAX_DELAY+1)
#define TENC 256
#define TDEC 64

// ---------------- kernel config ----------------
#define NBLK 128     // blocks (<=148 SMs -> all resident, barrier-safe)
#define NTHR 256     // threads per block
#define NC   4       // hidden columns per block (NBLK*NC == HH)
#define IROW 644     // padded input row stride (floats) -> conflict-free
#define WSI  648     // padded W_in column stride
#define WSH  520     // padded 512-row weight column stride

struct Smem {
    // float4-accessed arrays first (16B-aligned offsets)
    float inp[BB * IROW];          // staged activations (32 x up-to-640)
    float w_in [NC * WSI];         // W_in[:, jb..jb+3] transposed (col-major)
    float w_ps [NC * WSH];
    float w_tu [NC * WSH];
    float w_me [NC * WSH];
    float w_ot [HH];               // W_out[:, blk] (blocks 0..63 only)
    // scalar-accessed
    float buf[BB * NC * DD];       // circular delay buffer, stride 17 (odd -> conflict-free)
    float h1s[BB * NC];
    float hs [BB * NC];
    float psA[NTHR];
    float psB[NTHR];
    float psO[64];
    float sb_in[NC], sb_ps[NC], sb_tu[NC], sb_me[NC];
    float sb_ot;
    int   len[BB];
};

__device__ float g_h0[BB * HH];
__device__ float g_h1[BB * HH];
__device__ float g_hx[BB * HH];
__device__ unsigned g_arr;
__device__ unsigned g_gen;

// sense-reversing grid barrier (all NBLK blocks resident by construction)
__device__ __forceinline__ void grid_sync() {
    __syncthreads();
    if (threadIdx.x == 0) {
        volatile unsigned* vg = &g_gen;
        unsigned gen = *vg;
        __threadfence();                       // release my block's stores (cumulative)
        if (atomicAdd(&g_arr, 1u) == NBLK - 1u) {
            g_arr = 0u;
            __threadfence();
            atomicAdd(&g_gen, 1u);
        } else {
            while (*vg == gen) { }
            __threadfence();                   // acquire
        }
    }
    __syncthreads();
}

// one recurrence step (encode: DEC=false uses x_t + mask; decode: DEC=true, emits out)
template<bool DEC>
__device__ __forceinline__ void rnn_step(
    Smem* s, const float* __restrict__ x, float* __restrict__ out,
    int g, int t, int jb, int blk, int tid, int c, int b, int half)
{
    // ================= phase 1: h1 = [h0, x_t] @ W_in + b_in =================
    for (int i = tid; i < BB * (HH / 4); i += NTHR) {
        int rb = i >> 7, k4 = i & 127;
        float4 v = __ldcg(reinterpret_cast<const float4*>(g_h0 + rb * HH + (k4 << 2)));
        *reinterpret_cast<float4*>(s->inp + rb * IROW + (k4 << 2)) = v;
    }
    if (!DEC) {
        for (int i = tid; i < BB * (II / 4); i += NTHR) {
            int rb = i >> 5, k4 = i & 31;
            float4 v = *reinterpret_cast<const float4*>(
                x + (size_t)rb * (SS * II) + (size_t)t * II + (k4 << 2));
            *reinterpret_cast<float4*>(s->inp + rb * IROW + HH + (k4 << 2)) = v;
        }
    }
    __syncthreads();
    {
        const int K2 = (DEC ? HH : (HH + II)) >> 1;
        const float4* wp = reinterpret_cast<const float4*>(s->w_in + c * WSI + half * K2);
        const float4* ip = reinterpret_cast<const float4*>(s->inp + b * IROW + half * K2);
        float a0 = 0.f, a1 = 0.f, a2 = 0.f, a3 = 0.f;
        if (DEC && blk < CC) {
            // fold out = h0 @ W_out into the same k-loop (block-uniform branch)
            const float4* op = reinterpret_cast<const float4*>(s->w_ot + half * K2);
            float o0 = 0.f, o1 = 0.f, o2 = 0.f, o3 = 0.f;
            #pragma unroll 8
            for (int i = 0; i < K2 / 4; ++i) {
                float4 w = wp[i], v = ip[i], wo = op[i];
                a0 = fmaf(w.x, v.x, a0);  a1 = fmaf(w.y, v.y, a1);
                a2 = fmaf(w.z, v.z, a2);  a3 = fmaf(w.w, v.w, a3);
                o0 = fmaf(wo.x, v.x, o0); o1 = fmaf(wo.y, v.y, o1);
                o2 = fmaf(wo.z, v.z, o2); o3 = fmaf(wo.w, v.w, o3);
            }
            if (c == 0) s->psO[(half << 5) | b] = (o0 + o1) + (o2 + o3);
            s->psA[tid] = (a0 + a1) + (a2 + a3);
        } else {
            #pragma unroll 8
            for (int i = 0; i < K2 / 4; ++i) {
                float4 w = wp[i], v = ip[i];
                a0 = fmaf(w.x, v.x, a0); a1 = fmaf(w.y, v.y, a1);
                a2 = fmaf(w.z, v.z, a2); a3 = fmaf(w.w, v.w, a3);
            }
            s->psA[tid] = (a0 + a1) + (a2 + a3);
        }
    }
    __syncthreads();
    if (tid < 128) {
        float h1 = s->psA[tid] + s->psA[tid + 128] + s->sb_in[c];
        s->h1s[(b << 2) | c] = h1;
        __stcg(&g_h1[b * HH + jb + c], h1);
    }
    if (DEC && blk < CC && tid < BB) {
        float ov = s->psO[tid] + s->psO[tid + 32] + s->sb_ot;
        out[tid * (TDEC * CC) + t * CC + blk] = ov;
    }
    grid_sync();

    // ================= phase 2: p = h1 @ W_pass + b_pass; h = m*p+(1-m)*h1 ===
    for (int i = tid; i < BB * (HH / 4); i += NTHR) {
        int rb = i >> 7, k4 = i & 127;
        float4 v = __ldcg(reinterpret_cast<const float4*>(g_h1 + rb * HH + (k4 << 2)));
        *reinterpret_cast<float4*>(s->inp + rb * IROW + (k4 << 2)) = v;
    }
    __syncthreads();
    {
        const int K2 = HH >> 1;
        const float4* wp = reinterpret_cast<const float4*>(s->w_ps + c * WSH + half * K2);
        const float4* ip = reinterpret_cast<const float4*>(s->inp + b * IROW + half * K2);
        float a0 = 0.f, a1 = 0.f, a2 = 0.f, a3 = 0.f;
        #pragma unroll 8
        for (int i = 0; i < K2 / 4; ++i) {
            float4 w = wp[i], v = ip[i];
            a0 = fmaf(w.x, v.x, a0); a1 = fmaf(w.y, v.y, a1);
            a2 = fmaf(w.z, v.z, a2); a3 = fmaf(w.w, v.w, a3);
        }
        s->psA[tid] = (a0 + a1) + (a2 + a3);
    }
    __syncthreads();
    if (tid < 128) {
        float p = s->psA[tid] + s->psA[tid + 128] + s->sb_ps[c];
        float hv;
        if (DEC) hv = p;
        else     hv = (t < s->len[b]) ? p : s->h1s[(b << 2) | c];  // m in {0,1} -> exact select
        s->hs[(b << 2) | c] = hv;
        __stcg(&g_hx[b * HH + jb + c], hv);
    }
    grid_sync();

    // ============ phase 3: tau/mem gemms + circular buffer update ============
    for (int i = tid; i < BB * (HH / 4); i += NTHR) {
        int rb = i >> 7, k4 = i & 127;
        float4 v = __ldcg(reinterpret_cast<const float4*>(g_hx + rb * HH + (k4 << 2)));
        *reinterpret_cast<float4*>(s->inp + rb * IROW + (k4 << 2)) = v;
    }
    __syncthreads();
    {
        const int K2 = HH >> 1;
        const float4* wt = reinterpret_cast<const float4*>(s->w_tu + c * WSH + half * K2);
        const float4* wm = reinterpret_cast<const float4*>(s->w_me + c * WSH + half * K2);
        const float4* ip = reinterpret_cast<const float4*>(s->inp + b * IROW + half * K2);
        float a0 = 0.f, a1 = 0.f, a2 = 0.f, a3 = 0.f;
        float m0 = 0.f, m1 = 0.f, m2 = 0.f, m3 = 0.f;
        #pragma unroll 4
        for (int i = 0; i < K2 / 4; ++i) {
            float4 v = ip[i];
            float4 w = wt[i];
            a0 = fmaf(w.x, v.x, a0); a1 = fmaf(w.y, v.y, a1);
            a2 = fmaf(w.z, v.z, a2); a3 = fmaf(w.w, v.w, a3);
            float4 u = wm[i];
            m0 = fmaf(u.x, v.x, m0); m1 = fmaf(u.y, v.y, m1);
            m2 = fmaf(u.z, v.z, m2); m3 = fmaf(u.w, v.w, m3);
        }
        s->psA[tid] = (a0 + a1) + (a2 + a3);
        s->psB[tid] = (m0 + m1) + (m2 + m3);
    }
    __syncthreads();
    if (tid < 128) {
        float tl = s->psA[tid] + s->psA[tid + 128] + s->sb_tu[c];
        float ml = s->psB[tid] + s->psB[tid + 128] + s->sb_me[c];
        float tau = 16.f / (1.f + expf(-tl));
        tau = fminf(fmaxf(tau, 1.f), 16.f);
        float mem = 1.f / (1.f + expf(-ml));
        float hv  = s->hs[(b << 2) | c];
        float* bf = s->buf + ((b << 2) | c) * DD;
        // logical k at step g lives at phys (g+k)%17; newbuf[16]=0 -> zero slot g%17,
        // add w_d*h into phys (g+d)%17 for d=1..16, next h0 = phys (g+1)%17
        int s0 = g % DD;
        bf[s0] = 0.f;
        int sl = s0;
        #pragma unroll
        for (int d = 1; d <= 16; ++d) {
            ++sl; if (sl == DD) sl = 0;
            float w = mem / (1.f + fabsf(tau - (float)d));
            bf[sl] = fmaf(w, hv, bf[sl]);
        }
        int s1 = s0 + 1; if (s1 == DD) s1 = 0;
        __stcg(&g_h0[b * HH + jb + c], bf[s1]);
    }
    grid_sync();
}

__global__ void __launch_bounds__(NTHR, 1)
delay_rnn_kernel(const float* __restrict__ x,
                 const int*   __restrict__ lengths,
                 const float* __restrict__ Win,  const float* __restrict__ b_in,
                 const float* __restrict__ Wps,  const float* __restrict__ b_ps,
                 const float* __restrict__ Wtu,  const float* __restrict__ b_tu,
                 const float* __restrict__ Wme,  const float* __restrict__ b_me,
                 const float* __restrict__ Wot,  const float* __restrict__ b_ot,
                 float* __restrict__ out)
{
    extern __shared__ __align__(16) char smem_raw[];
    Smem* s = reinterpret_cast<Smem*>(smem_raw);
    const int tid  = threadIdx.x;
    const int blk  = blockIdx.x;
    const int jb   = blk * NC;
    const int c    = tid & 3;
    const int b    = (tid >> 2) & 31;
    const int half = tid >> 7;

    // -------- one-time setup: weights -> smem (transposed, padded) --------
    for (int i = tid; i < (HH + II) * NC; i += NTHR) {
        int cc = i & 3, k = i >> 2;
        s->w_in[cc * WSI + k] = Win[k * HH + jb + cc];
    }
    for (int i = tid; i < HH * NC; i += NTHR) {
        int cc = i & 3, k = i >> 2;
        s->w_ps[cc * WSH + k] = Wps[k * HH + jb + cc];
        s->w_tu[cc * WSH + k] = Wtu[k * HH + jb + cc];
        s->w_me[cc * WSH + k] = Wme[k * HH + jb + cc];
    }
    if (blk < CC)
        for (int k = tid; k < HH; k += NTHR) s->w_ot[k] = Wot[k * CC + blk];
    if (tid < NC) {
        s->sb_in[tid] = b_in[jb + tid];
        s->sb_ps[tid] = b_ps[jb + tid];
        s->sb_tu[tid] = b_tu[jb + tid];
        s->sb_me[tid] = b_me[jb + tid];
    }
    if (tid == 0) s->sb_ot = (blk < CC) ? b_ot[blk] : 0.f;
    if (tid < BB) s->len[tid] = lengths[tid];
    for (int i = tid; i < BB * NC * DD; i += NTHR) s->buf[i] = 0.f;
    if (tid < 128) __stcg(&g_h0[b * HH + jb + c], 0.f);   // buffer[:,:,0] starts zero
    grid_sync();

    // -------- encode: 256 steps --------
    for (int g = 0; g < TENC; ++g)
        rnn_step<false>(s, x, out, g, g, jb, blk, tid, c, b, half);
    // -------- decode: 64 steps --------
    for (int g = TENC; g < TENC + TDEC; ++g)
        rnn_step<true>(s, x, out, g, g - TENC, jb, blk, tid, c, b, half);
}

extern "C" void kernel_launch(void* const* d_in, const int* in_sizes, int n_in,
                              void* d_out, int out_size) {
    const float* x       = (const float*)d_in[0];
    const int*   lengths = (const int*)d_in[1];
    // locate W_in robustly (out_lengths scalar may or may not occupy index 2)
    int wi = -1;
    for (int i = 2; i < n_in; ++i)
        if (in_sizes[i] == (HH + II) * HH) { wi = i; break; }
    if (wi < 0) wi = 3;
    const float* Win  = (const float*)d_in[wi + 0];
    const float* b_in = (const float*)d_in[wi + 1];
    const float* Wps  = (const float*)d_in[wi + 2];
    const float* b_ps = (const float*)d_in[wi + 3];
    const float* Wtu  = (const float*)d_in[wi + 4];
    const float* b_tu = (const float*)d_in[wi + 5];
    const float* Wme  = (const float*)d_in[wi + 6];
    const float* b_me = (const float*)d_in[wi + 7];
    const float* Wot  = (const float*)d_in[wi + 8];
    const float* b_ot = (const float*)d_in[wi + 9];
    float* out = (float*)d_out;

    size_t smem = sizeof(Smem);
    cudaFuncSetAttribute(delay_rnn_kernel,
                         cudaFuncAttributeMaxDynamicSharedMemorySize, (int)smem);
    delay_rnn_kernel<<<NBLK, NTHR, smem>>>(x, lengths, Win, b_in, Wps, b_ps,
                                           Wtu, b_tu, Wme, b_me, Wot, b_ot, out);
}

// round 13
// speedup vs baseline: 1.2835x; 1.2799x over previous
#include <cuda_runtime.h>

// ---------------- problem constants ----------------
#define BB   32      // batch
#define SS   256     // seq len
#define II   128     // input dim
#define HH   512     // hidden
#define CC   64      // out channels
#define DD   17      // buffer depth (MAX_DELAY+1)
#define TENC 256
#define TDEC 64

// ---------------- kernel config (R9 constants, unchanged) ----------------
#define NBLK 128     // blocks (<=148 SMs -> all resident, barrier-safe)
#define NTHR 256     // threads per block
#define NC   4       // hidden columns per block (NBLK*NC == HH)
#define IROW 644     // padded input row stride (floats) -> conflict-free
#define WSI  648     // padded W_in/W_comb column stride
#define WSH  520     // padded 512-row weight column stride

struct Smem {
    // float4-accessed arrays first (16B-aligned offsets)
    float inp[BB * IROW];          // staged activations (32 x up-to-640)
    float w_in[NC * WSI];          // W_in[:, jb..jb+3] transposed (col-major)
    float w_cm[NC * WSI];          // W_comb[:, jb..jb+3] transposed (col-major)
    float w_tu[NC * WSH];
    float w_me[NC * WSH];
    float w_ot[HH];                // W_out[:, blk] (blocks 0..63 only)
    // scalar-accessed
    float buf[BB * NC * DD];       // circular delay buffer, stride 17 (odd -> conflict-free)
    float hs [BB * NC];
    float psA[NTHR];
    float psB[NTHR];
    float psO[64];
    float sb_in[NC], sb_cm[NC], sb_tu[NC], sb_me[NC];
    float sb_ot;
    int   len[BB];
};

__device__ float g_h0[BB * HH];
__device__ float g_hx[BB * HH];
__device__ float g_wcomb[(HH + II) * HH];   // W_in @ W_pass, (640,512) row-major
__device__ float g_bcomb[HH];               // b_in @ W_pass + b_pass
__device__ unsigned g_arr;
__device__ unsigned g_gen;

// ---------------- pre-kernel 1: W_comb = W_in @ W_pass ----------------
// 160 blocks x 256 threads; block bb computes rows 4bb..4bb+3 of W_comb.
__global__ void build_wcomb(const float* __restrict__ Win,
                            const float* __restrict__ Wps) {
    __shared__ float a[4][HH];
    int r0 = blockIdx.x * 4;
    for (int i = threadIdx.x; i < 4 * HH; i += 256)
        a[i / HH][i % HH] = Win[(size_t)(r0 + i / HH) * HH + (i % HH)];
    __syncthreads();
    int c0 = threadIdx.x * 2;                 // thread owns cols c0, c0+1
    float a00 = 0.f, a01 = 0.f, a10 = 0.f, a11 = 0.f;
    float a20 = 0.f, a21 = 0.f, a30 = 0.f, a31 = 0.f;
    #pragma unroll 8
    for (int k = 0; k < HH; ++k) {
        float2 w = *reinterpret_cast<const float2*>(Wps + (size_t)k * HH + c0);
        a00 = fmaf(a[0][k], w.x, a00); a01 = fmaf(a[0][k], w.y, a01);
        a10 = fmaf(a[1][k], w.x, a10); a11 = fmaf(a[1][k], w.y, a11);
        a20 = fmaf(a[2][k], w.x, a20); a21 = fmaf(a[2][k], w.y, a21);
        a30 = fmaf(a[3][k], w.x, a30); a31 = fmaf(a[3][k], w.y, a31);
    }
    g_wcomb[(size_t)(r0 + 0) * HH + c0] = a00; g_wcomb[(size_t)(r0 + 0) * HH + c0 + 1] = a01;
    g_wcomb[(size_t)(r0 + 1) * HH + c0] = a10; g_wcomb[(size_t)(r0 + 1) * HH + c0 + 1] = a11;
    g_wcomb[(size_t)(r0 + 2) * HH + c0] = a20; g_wcomb[(size_t)(r0 + 2) * HH + c0 + 1] = a21;
    g_wcomb[(size_t)(r0 + 3) * HH + c0] = a30; g_wcomb[(size_t)(r0 + 3) * HH + c0 + 1] = a31;
}

// ---------------- pre-kernel 2: b_comb = b_in @ W_pass + b_pass ----------------
__global__ void build_bcomb(const float* __restrict__ bin,
                            const float* __restrict__ Wps,
                            const float* __restrict__ bps) {
    int c = blockIdx.x * 256 + threadIdx.x;   // 2 blocks x 256 = 512 cols
    float acc = bps[c];
    #pragma unroll 8
    for (int k = 0; k < HH; ++k)
        acc = fmaf(bin[k], Wps[(size_t)k * HH + c], acc);
    g_bcomb[c] = acc;
}

// sense-reversing grid barrier (all NBLK blocks resident by construction)
__device__ __forceinline__ void grid_sync() {
    __syncthreads();
    if (threadIdx.x == 0) {
        volatile unsigned* vg = &g_gen;
        unsigned gen = *vg;
        __threadfence();                       // release my block's stores (cumulative)
        if (atomicAdd(&g_arr, 1u) == NBLK - 1u) {
            g_arr = 0u;
            __threadfence();
            atomicAdd(&g_gen, 1u);
        } else {
            while (*vg == gen) { __nanosleep(32); }
            __threadfence();                   // acquire
        }
    }
    __syncthreads();
}

// one recurrence step, two phases:
//   phase 1: h1 = [h0,x]@W_in, p = [h0,x]@W_comb (one k-loop), select -> h
//   phase 2: tau/mem gemms + circular buffer update
template<bool DEC>
__device__ __forceinline__ void rnn_step(
    Smem* s, const float* __restrict__ x, float* __restrict__ out,
    int g, int t, int jb, int blk, int tid, int c, int b, int half)
{
    // ================= phase 1 =================
    for (int i = tid; i < BB * (HH / 4); i += NTHR) {
        int rb = i >> 7, k4 = i & 127;
        float4 v = __ldcg(reinterpret_cast<const float4*>(g_h0 + rb * HH + (k4 << 2)));
        *reinterpret_cast<float4*>(s->inp + rb * IROW + (k4 << 2)) = v;
    }
    if (!DEC) {
        for (int i = tid; i < BB * (II / 4); i += NTHR) {
            int rb = i >> 5, k4 = i & 31;
            float4 v = *reinterpret_cast<const float4*>(
                x + (size_t)rb * (SS * II) + (size_t)t * II + (k4 << 2));
            *reinterpret_cast<float4*>(s->inp + rb * IROW + HH + (k4 << 2)) = v;
        }
    }
    __syncthreads();
    if (!DEC) {
        // encode: h1 and p in ONE k-loop over K=640
        const int K2 = (HH + II) >> 1;
        const float4* wi = reinterpret_cast<const float4*>(s->w_in + c * WSI + half * K2);
        const float4* wc = reinterpret_cast<const float4*>(s->w_cm + c * WSI + half * K2);
        const float4* ip = reinterpret_cast<const float4*>(s->inp + b * IROW + half * K2);
        float a0 = 0.f, a1 = 0.f, a2 = 0.f, a3 = 0.f;
        float p0 = 0.f, p1 = 0.f, p2 = 0.f, p3 = 0.f;
        #pragma unroll 8
        for (int i = 0; i < K2 / 4; ++i) {
            float4 v = ip[i];
            float4 w = wi[i];
            a0 = fmaf(w.x, v.x, a0); a1 = fmaf(w.y, v.y, a1);
            a2 = fmaf(w.z, v.z, a2); a3 = fmaf(w.w, v.w, a3);
            float4 u = wc[i];
            p0 = fmaf(u.x, v.x, p0); p1 = fmaf(u.y, v.y, p1);
            p2 = fmaf(u.z, v.z, p2); p3 = fmaf(u.w, v.w, p3);
        }
        s->psA[tid] = (a0 + a1) + (a2 + a3);
        s->psB[tid] = (p0 + p1) + (p2 + p3);
    } else {
        // decode: p = h0@W_comb[:512]  (+ fold out = h0@W_out for blocks < CC)
        const int K2 = HH >> 1;
        const float4* wc = reinterpret_cast<const float4*>(s->w_cm + c * WSI + half * K2);
        const float4* ip = reinterpret_cast<const float4*>(s->inp + b * IROW + half * K2);
        float p0 = 0.f, p1 = 0.f, p2 = 0.f, p3 = 0.f;
        if (blk < CC) {
            const float4* op = reinterpret_cast<const float4*>(s->w_ot + half * K2);
            float o0 = 0.f, o1 = 0.f, o2 = 0.f, o3 = 0.f;
            #pragma unroll 8
            for (int i = 0; i < K2 / 4; ++i) {
                float4 v = ip[i];
                float4 u = wc[i];
                p0 = fmaf(u.x, v.x, p0); p1 = fmaf(u.y, v.y, p1);
                p2 = fmaf(u.z, v.z, p2); p3 = fmaf(u.w, v.w, p3);
                float4 wo = op[i];
                o0 = fmaf(wo.x, v.x, o0); o1 = fmaf(wo.y, v.y, o1);
                o2 = fmaf(wo.z, v.z, o2); o3 = fmaf(wo.w, v.w, o3);
            }
            if (c == 0) s->psO[(half << 5) | b] = (o0 + o1) + (o2 + o3);
            s->psB[tid] = (p0 + p1) + (p2 + p3);
        } else {
            #pragma unroll 8
            for (int i = 0; i < K2 / 4; ++i) {
                float4 v = ip[i];
                float4 u = wc[i];
                p0 = fmaf(u.x, v.x, p0); p1 = fmaf(u.y, v.y, p1);
                p2 = fmaf(u.z, v.z, p2); p3 = fmaf(u.w, v.w, p3);
            }
            s->psB[tid] = (p0 + p1) + (p2 + p3);
        }
    }
    __syncthreads();
    if (tid < 128) {
        float p = s->psB[tid] + s->psB[tid + 128] + s->sb_cm[c];
        float hv;
        if (DEC) hv = p;
        else {
            float h1 = s->psA[tid] + s->psA[tid + 128] + s->sb_in[c];
            hv = (t < s->len[b]) ? p : h1;     // m in {0,1} -> exact select
        }
        s->hs[(b << 2) | c] = hv;
        __stcg(&g_hx[b * HH + jb + c], hv);
    }
    if (DEC && blk < CC && tid < BB) {
        float ov = s->psO[tid] + s->psO[tid + 32] + s->sb_ot;
        out[tid * (TDEC * CC) + t * CC + blk] = ov;
    }
    grid_sync();

    // ============ phase 2: tau/mem gemms + circular buffer update ============
    for (int i = tid; i < BB * (HH / 4); i += NTHR) {
        int rb = i >> 7, k4 = i & 127;
        float4 v = __ldcg(reinterpret_cast<const float4*>(g_hx + rb * HH + (k4 << 2)));
        *reinterpret_cast<float4*>(s->inp + rb * IROW + (k4 << 2)) = v;
    }
    __syncthreads();
    {
        const int K2 = HH >> 1;
        const float4* wt = reinterpret_cast<const float4*>(s->w_tu + c * WSH + half * K2);
        const float4* wm = reinterpret_cast<const float4*>(s->w_me + c * WSH + half * K2);
        const float4* ip = reinterpret_cast<const float4*>(s->inp + b * IROW + half * K2);
        float a0 = 0.f, a1 = 0.f, a2 = 0.f, a3 = 0.f;
        float m0 = 0.f, m1 = 0.f, m2 = 0.f, m3 = 0.f;
        #pragma unroll 4
        for (int i = 0; i < K2 / 4; ++i) {
            float4 v = ip[i];
            float4 w = wt[i];
            a0 = fmaf(w.x, v.x, a0); a1 = fmaf(w.y, v.y, a1);
            a2 = fmaf(w.z, v.z, a2); a3 = fmaf(w.w, v.w, a3);
            float4 u = wm[i];
            m0 = fmaf(u.x, v.x, m0); m1 = fmaf(u.y, v.y, m1);
            m2 = fmaf(u.z, v.z, m2); m3 = fmaf(u.w, v.w, m3);
        }
        s->psA[tid] = (a0 + a1) + (a2 + a3);
        s->psB[tid] = (m0 + m1) + (m2 + m3);
    }
    __syncthreads();
    if (tid < 128) {
        float tl = s->psA[tid] + s->psA[tid + 128] + s->sb_tu[c];
        float ml = s->psB[tid] + s->psB[tid + 128] + s->sb_me[c];
        float tau = 16.f / (1.f + expf(-tl));
        tau = fminf(fmaxf(tau, 1.f), 16.f);
        float mem = 1.f / (1.f + expf(-ml));
        float hv  = s->hs[(b << 2) | c];
        float* bf = s->buf + ((b << 2) | c) * DD;
        // logical k at step g lives at phys (g+k)%17; newbuf[16]=0 -> zero slot g%17,
        // add w_d*h into phys (g+d)%17 for d=1..16, next h0 = phys (g+1)%17
        int s0 = g % DD;
        bf[s0] = 0.f;
        int sl = s0;
        #pragma unroll
        for (int d = 1; d <= 16; ++d) {
            ++sl; if (sl == DD) sl = 0;
            float w = mem / (1.f + fabsf(tau - (float)d));
            bf[sl] = fmaf(w, hv, bf[sl]);
        }
        int s1 = s0 + 1; if (s1 == DD) s1 = 0;
        __stcg(&g_h0[b * HH + jb + c], bf[s1]);
    }
    grid_sync();
}

__global__ void __launch_bounds__(NTHR, 1)
delay_rnn_kernel(const float* __restrict__ x,
                 const int*   __restrict__ lengths,
                 const float* __restrict__ Win,  const float* __restrict__ b_in,
                 const float* __restrict__ Wtu,  const float* __restrict__ b_tu,
                 const float* __restrict__ Wme,  const float* __restrict__ b_me,
                 const float* __restrict__ Wot,  const float* __restrict__ b_ot,
                 float* __restrict__ out)
{
    extern __shared__ __align__(16) char smem_raw[];
    Smem* s = reinterpret_cast<Smem*>(smem_raw);
    const int tid  = threadIdx.x;
    const int blk  = blockIdx.x;
    const int jb   = blk * NC;
    const int c    = tid & 3;
    const int b    = (tid >> 2) & 31;
    const int half = tid >> 7;

    // -------- one-time setup: weights -> smem (transposed, padded) --------
    for (int i = tid; i < (HH + II) * NC; i += NTHR) {
        int cc = i & 3, k = i >> 2;
        s->w_in[cc * WSI + k] = Win[(size_t)k * HH + jb + cc];
        s->w_cm[cc * WSI + k] = g_wcomb[(size_t)k * HH + jb + cc];
    }
    for (int i = tid; i < HH * NC; i += NTHR) {
        int cc = i & 3, k = i >> 2;
        s->w_tu[cc * WSH + k] = Wtu[(size_t)k * HH + jb + cc];
        s->w_me[cc * WSH + k] = Wme[(size_t)k * HH + jb + cc];
    }
    if (blk < CC)
        for (int k = tid; k < HH; k += NTHR) s->w_ot[k] = Wot[(size_t)k * CC + blk];
    if (tid < NC) {
        s->sb_in[tid] = b_in[jb + tid];
        s->sb_cm[tid] = g_bcomb[jb + tid];
        s->sb_tu[tid] = b_tu[jb + tid];
        s->sb_me[tid] = b_me[jb + tid];
    }
    if (tid == 0) s->sb_ot = (blk < CC) ? b_ot[blk] : 0.f;
    if (tid < BB) s->len[tid] = lengths[tid];
    for (int i = tid; i < BB * NC * DD; i += NTHR) s->buf[i] = 0.f;
    if (tid < 128) __stcg(&g_h0[b * HH + jb + c], 0.f);   // buffer[:,:,0] starts zero
    grid_sync();

    // -------- encode: 256 steps --------
    for (int g = 0; g < TENC; ++g)
        rnn_step<false>(s, x, out, g, g, jb, blk, tid, c, b, half);
    // -------- decode: 64 steps --------
    for (int g = TENC; g < TENC + TDEC; ++g)
        rnn_step<true>(s, x, out, g, g - TENC, jb, blk, tid, c, b, half);
}

extern "C" void kernel_launch(void* const* d_in, const int* in_sizes, int n_in,
                              void* d_out, int out_size) {
    const float* x       = (const float*)d_in[0];
    const int*   lengths = (const int*)d_in[1];
    // locate W_in robustly (out_lengths scalar may or may not occupy index 2)
    int wi = -1;
    for (int i = 2; i < n_in; ++i)
        if (in_sizes[i] == (HH + II) * HH) { wi = i; break; }
    if (wi < 0) wi = 3;
    const float* Win  = (const float*)d_in[wi + 0];
    const float* b_in = (const float*)d_in[wi + 1];
    const float* Wps  = (const float*)d_in[wi + 2];
    const float* b_ps = (const float*)d_in[wi + 3];
    const float* Wtu  = (const float*)d_in[wi + 4];
    const float* b_tu = (const float*)d_in[wi + 5];
    const float* Wme  = (const float*)d_in[wi + 6];
    const float* b_me = (const float*)d_in[wi + 7];
    const float* Wot  = (const float*)d_in[wi + 8];
    const float* b_ot = (const float*)d_in[wi + 9];
    float* out = (float*)d_out;

    // pre-kernels: W_comb = W_in @ W_pass, b_comb = b_in @ W_pass + b_pass
    build_wcomb<<<(HH + II) / 4, 256>>>(Win, Wps);
    build_bcomb<<<HH / 256, 256>>>(b_in, Wps, b_ps);

    size_t smem = sizeof(Smem);
    cudaFuncSetAttribute(delay_rnn_kernel,
                         cudaFuncAttributeMaxDynamicSharedMemorySize, (int)smem);
    delay_rnn_kernel<<<NBLK, NTHR, smem>>>(x, lengths, Win, b_in,
                                           Wtu, b_tu, Wme, b_me, Wot, b_ot, out);
}